// round 4
// baseline (speedup 1.0000x reference)
#include <cuda_runtime.h>

#define BSZ    2048
#define TT     128
#define NN     256
#define MM     256
#define KK2    512      /* 2M */
#define GG4    1024     /* 4M */
#define B_TILE 16
#define NBLK   (BSZ / B_TILE)   /* 128 */
#define NTHR   512

// Scratch: Ux[b][s][n] = sum_t x[b,t,n] * U_e[s,t]   (268 MB, module-load static)
__device__ float g_Ux[BSZ * TT * NN];

// ---------------- fast math helpers ----------------
__device__ __forceinline__ float ex2f(float x) {
    float r; asm("ex2.approx.f32 %0, %1;" : "=f"(r) : "f"(x)); return r;
}
__device__ __forceinline__ float rcpf(float x) {
    float r; asm("rcp.approx.f32 %0, %1;" : "=f"(r) : "f"(x)); return r;
}
#define L2E 1.4426950408889634f

// tanh(x) = 1 - 2/(e^{2x}+1); ex2/rcp approx -> ~1e-6 abs error, inf-safe.
__device__ __forceinline__ float tanh_fast(float x) {
    float t = ex2f(2.0f * L2E * x);
    return 1.0f - 2.0f * rcpf(t + 1.0f);
}
// sigmoid(x) = 1/(1+e^{-x}); ex2 overflow -> inf -> rcp -> 0 (correct limit).
__device__ __forceinline__ float sigmoid_fast(float x) {
    return rcpf(1.0f + ex2f(-L2E * x));
}

// ---------------- packed f32x2 FMA ----------------
typedef unsigned long long u64;
__device__ __forceinline__ u64 pack2(float a, float b) {
    u64 r; asm("mov.b64 %0, {%1, %2};" : "=l"(r) : "f"(a), "f"(b)); return r;
}
__device__ __forceinline__ void unpack2(u64 v, float& a, float& b) {
    asm("mov.b64 {%0, %1}, %2;" : "=f"(a), "=f"(b) : "l"(v));
}
__device__ __forceinline__ u64 ffma2(u64 a, u64 b, u64 c) {
    u64 d; asm("fma.rn.f32x2 %0, %1, %2, %3;" : "=l"(d) : "l"(a), "l"(b), "l"(c)); return d;
}

// =====================================================================
// Kernel 1: UxT[b][s][n] = sum_t U_e[s][t] * x[b][t][n]
// grid = 2048 (one batch per block), 256 threads (thread = n)
// smem: x_b [T][N] (128 KB) + U_e [T][T] (64 KB)
// =====================================================================
__global__ void __launch_bounds__(256, 1) ux_kernel(
    const float* __restrict__ x, const float* __restrict__ U_e)
{
    extern __shared__ float sm[];
    float* x_s = sm;             // [TT][NN]
    float* U_s = sm + TT * NN;   // [TT][TT]  (s-major: U_s[s*TT+t])

    const int b   = blockIdx.x;
    const int tid = threadIdx.x;

    const float4* xg  = (const float4*)(x + (size_t)b * TT * NN);
    float4*       xs4 = (float4*)x_s;
    for (int i = tid; i < TT * NN / 4; i += 256) xs4[i] = xg[i];
    const float4* ug  = (const float4*)U_e;
    float4*       us4 = (float4*)U_s;
    for (int i = tid; i < TT * TT / 4; i += 256) us4[i] = ug[i];
    __syncthreads();

    const int n = tid;
    for (int chunk = 0; chunk < 8; chunk++) {
        float acc[16];
        #pragma unroll
        for (int i = 0; i < 16; i++) acc[i] = 0.0f;
        #pragma unroll 4
        for (int t = 0; t < TT; t++) {
            float xv = x_s[t * NN + n];
            #pragma unroll
            for (int i = 0; i < 16; i++)
                acc[i] = fmaf(U_s[(chunk * 16 + i) * TT + t], xv, acc[i]);
        }
        #pragma unroll
        for (int i = 0; i < 16; i++) {
            int s = chunk * 16 + i;
            g_Ux[((size_t)b * TT + s) * NN + n] = acc[i];
        }
    }
}

// =====================================================================
// Kernel 2: persistent recurrence. grid = 128 blocks x 16 batches, 512 thr.
// =====================================================================
__global__ void __launch_bounds__(NTHR, 1) rec_kernel(
    const float* __restrict__ W_e,  const float* __restrict__ V_e,
    const float* __restrict__ W_ih, const float* __restrict__ W_hh,
    const float* __restrict__ b_ih, const float* __restrict__ b_hh,
    float* __restrict__ out)
{
    extern __shared__ float sm[];
    float* h_s   = sm;                     // [NN][B_TILE]
    float* c_s   = h_s   + NN * B_TILE;    // [NN][B_TILE]
    float* xt_s  = c_s   + NN * B_TILE;    // [NN][B_TILE]
    float* whs_s = xt_s  + NN * B_TILE;    // [TT][B_TILE]
    float* e_s   = whs_s + TT * B_TILE;    // [B_TILE][NN]
    float* V_s   = e_s   + B_TILE * NN;    // [TT]
    float* bs_s  = V_s   + TT;             // [GG4]

    const int tid = threadIdx.x;
    const int b0  = blockIdx.x * B_TILE;

    for (int i = tid; i < NN * B_TILE; i += NTHR) { h_s[i] = 0.0f; c_s[i] = 0.0f; }
    for (int i = tid; i < TT;  i += NTHR) V_s[i]  = V_e[i];
    for (int i = tid; i < GG4; i += NTHR) bs_s[i] = b_ih[i] + b_hh[i];
    __syncthreads();

    // phase A (whs): thread = (sI, 4 batches)
    const int sI  = tid & (TT - 1);
    const int j0A = (tid >> 7) * 4;                 // 0,4,8,12
    // phase B (attention): thread = (n, 8 batches)
    const int nB  = tid & (NN - 1);
    const int j0B = (tid >> 8) * 8;                 // 0 or 8
    // phase C (softmax): warp = batch
    const int warp = tid >> 5, lane = tid & 31;
    // phase D (gates): thread = (m, 8 batches)
    const int mD  = tid & (NN - 1);
    const int jD0 = (tid >> 8) * 8;

    // Ux row pointers (t-invariant)
    const float* uxp[8];
    #pragma unroll
    for (int jj = 0; jj < 8; jj++)
        uxp[jj] = g_Ux + (size_t)(b0 + j0B + jj) * TT * NN + nB;

    // per-thread weight rows (float4-streamed, L1 reuse 8x per line)
    const float4* weR = (const float4*)(W_e + (size_t)sI * KK2);
    const float4* wih[4]; const float4* whh[4];
    #pragma unroll
    for (int g = 0; g < 4; g++) {
        wih[g] = (const float4*)(W_ih + (size_t)(g * MM + mD) * NN);
        whh[g] = (const float4*)(W_hh + (size_t)(g * MM + mD) * MM);
    }

    for (int t = 0; t < TT; t++) {
        // ---------- Phase A: whs[sI][j] = [h;c] . W_e[sI] ----------
        {
            u64 a01 = 0ull, a23 = 0ull;   // bit pattern of (0.f,0.f)
            #pragma unroll 4
            for (int k4 = 0; k4 < NN / 4; k4++) {
                float4 w = weR[k4];
                #pragma unroll
                for (int q = 0; q < 4; q++) {
                    int k = k4 * 4 + q;
                    float wq = (&w.x)[q];
                    u64 wp = pack2(wq, wq);
                    ulonglong2 hv = *(const ulonglong2*)&h_s[k * B_TILE + j0A];
                    a01 = ffma2(wp, hv.x, a01);
                    a23 = ffma2(wp, hv.y, a23);
                }
            }
            #pragma unroll 4
            for (int k4 = 0; k4 < NN / 4; k4++) {
                float4 w = weR[NN / 4 + k4];
                #pragma unroll
                for (int q = 0; q < 4; q++) {
                    int k = k4 * 4 + q;
                    float wq = (&w.x)[q];
                    u64 wp = pack2(wq, wq);
                    ulonglong2 cv = *(const ulonglong2*)&c_s[k * B_TILE + j0A];
                    a01 = ffma2(wp, cv.x, a01);
                    a23 = ffma2(wp, cv.y, a23);
                }
            }
            float4 r;
            unpack2(a01, r.x, r.y);
            unpack2(a23, r.z, r.w);
            *(float4*)&whs_s[sI * B_TILE + j0A] = r;
        }
        __syncthreads();

        // ---------- Phase B: e[j][n] = sum_s V[s] * tanh(Ux + whs) ----------
        {
            float eacc[8] = {0, 0, 0, 0, 0, 0, 0, 0};
            #pragma unroll 2
            for (int s = 0; s < TT; s++) {
                float4 w0 = *(const float4*)&whs_s[s * B_TILE + j0B];
                float4 w1 = *(const float4*)&whs_s[s * B_TILE + j0B + 4];
                float vs = V_s[s];
                float wv[8] = {w0.x, w0.y, w0.z, w0.w, w1.x, w1.y, w1.z, w1.w};
                #pragma unroll
                for (int jj = 0; jj < 8; jj++) {
                    float u = __ldg(uxp[jj] + (size_t)s * NN);
                    eacc[jj] = fmaf(vs, tanh_fast(u + wv[jj]), eacc[jj]);
                }
            }
            #pragma unroll
            for (int jj = 0; jj < 8; jj++)
                e_s[(j0B + jj) * NN + nB] = eacc[jj];
        }
        __syncthreads();

        // ---------- Phase C: softmax over n, xt = alpha * e ----------
        {
            const int j = warp;   // 16 warps == B_TILE
            float ev[8];
            float mx = -3.4e38f;
            #pragma unroll
            for (int i = 0; i < 8; i++) {
                ev[i] = e_s[j * NN + lane + 32 * i];
                mx = fmaxf(mx, ev[i]);
            }
            #pragma unroll
            for (int o = 16; o > 0; o >>= 1) mx = fmaxf(mx, __shfl_xor_sync(0xffffffffu, mx, o));
            float ax[8], sum = 0.0f;
            #pragma unroll
            for (int i = 0; i < 8; i++) { ax[i] = ex2f((ev[i] - mx) * L2E); sum += ax[i]; }
            #pragma unroll
            for (int o = 16; o > 0; o >>= 1) sum += __shfl_xor_sync(0xffffffffu, sum, o);
            float inv = rcpf(sum);
            #pragma unroll
            for (int i = 0; i < 8; i++)
                xt_s[(lane + 32 * i) * B_TILE + j] = (ax[i] * inv) * ev[i];
        }
        __syncthreads();

        // ---------- Phase D: gates + LSTM update ----------
        {
            u64 acc[4][4];
            #pragma unroll
            for (int g = 0; g < 4; g++) {
                float bb = bs_s[g * MM + mD];
                u64 bp = pack2(bb, bb);
                #pragma unroll
                for (int p = 0; p < 4; p++) acc[g][p] = bp;
            }
            // xt @ W_ih^T
            #pragma unroll 2
            for (int k4 = 0; k4 < NN / 4; k4++) {
                float4 w0 = wih[0][k4], w1 = wih[1][k4], w2 = wih[2][k4], w3 = wih[3][k4];
                #pragma unroll
                for (int q = 0; q < 4; q++) {
                    int k = k4 * 4 + q;
                    ulonglong2 xa = *(const ulonglong2*)&xt_s[k * B_TILE + jD0];
                    ulonglong2 xb = *(const ulonglong2*)&xt_s[k * B_TILE + jD0 + 4];
                    float ws[4] = { (&w0.x)[q], (&w1.x)[q], (&w2.x)[q], (&w3.x)[q] };
                    #pragma unroll
                    for (int g = 0; g < 4; g++) {
                        u64 wp = pack2(ws[g], ws[g]);
                        acc[g][0] = ffma2(wp, xa.x, acc[g][0]);
                        acc[g][1] = ffma2(wp, xa.y, acc[g][1]);
                        acc[g][2] = ffma2(wp, xb.x, acc[g][2]);
                        acc[g][3] = ffma2(wp, xb.y, acc[g][3]);
                    }
                }
            }
            // h @ W_hh^T  (old h)
            #pragma unroll 2
            for (int k4 = 0; k4 < MM / 4; k4++) {
                float4 w0 = whh[0][k4], w1 = whh[1][k4], w2 = whh[2][k4], w3 = whh[3][k4];
                #pragma unroll
                for (int q = 0; q < 4; q++) {
                    int k = k4 * 4 + q;
                    ulonglong2 ha = *(const ulonglong2*)&h_s[k * B_TILE + jD0];
                    ulonglong2 hb = *(const ulonglong2*)&h_s[k * B_TILE + jD0 + 4];
                    float ws[4] = { (&w0.x)[q], (&w1.x)[q], (&w2.x)[q], (&w3.x)[q] };
                    #pragma unroll
                    for (int g = 0; g < 4; g++) {
                        u64 wp = pack2(ws[g], ws[g]);
                        acc[g][0] = ffma2(wp, ha.x, acc[g][0]);
                        acc[g][1] = ffma2(wp, ha.y, acc[g][1]);
                        acc[g][2] = ffma2(wp, hb.x, acc[g][2]);
                        acc[g][3] = ffma2(wp, hb.y, acc[g][3]);
                    }
                }
            }
            // read old cell state before anyone writes
            float cold[8];
            #pragma unroll
            for (int jj = 0; jj < 8; jj++) cold[jj] = c_s[mD * B_TILE + jD0 + jj];
            __syncthreads();   // all reads of h_s/xt_s/c_s complete

            #pragma unroll
            for (int p = 0; p < 4; p++) {
                float iv[2], fv[2], gv[2], ov[2];
                unpack2(acc[0][p], iv[0], iv[1]);
                unpack2(acc[1][p], fv[0], fv[1]);
                unpack2(acc[2][p], gv[0], gv[1]);
                unpack2(acc[3][p], ov[0], ov[1]);
                #pragma unroll
                for (int h2 = 0; h2 < 2; h2++) {
                    int jj = 2 * p + h2;
                    float cn = sigmoid_fast(fv[h2]) * cold[jj]
                             + sigmoid_fast(iv[h2]) * tanh_fast(gv[h2]);
                    float hn = sigmoid_fast(ov[h2]) * tanh_fast(cn);
                    c_s[mD * B_TILE + jD0 + jj] = cn;
                    h_s[mD * B_TILE + jD0 + jj] = hn;
                    out[(size_t)(b0 + jD0 + jj) * (MM * TT) + (size_t)mD * TT + t] = hn;
                }
            }
        }
        __syncthreads();   // state writes visible before next step's reads
    }
}

extern "C" void kernel_launch(void* const* d_in, const int* in_sizes, int n_in,
                              void* d_out, int out_size)
{
    const float* x    = (const float*)d_in[0];
    const float* W_e  = (const float*)d_in[1];
    const float* U_e  = (const float*)d_in[2];
    const float* V_e  = (const float*)d_in[3];
    const float* W_ih = (const float*)d_in[4];
    const float* W_hh = (const float*)d_in[5];
    const float* b_ih = (const float*)d_in[6];
    const float* b_hh = (const float*)d_in[7];
    float* out = (float*)d_out;

    const int smem1 = (TT * NN + TT * TT) * 4;                                   // 196608
    const int smem2 = (3 * NN * B_TILE + TT * B_TILE + B_TILE * NN + TT + GG4) * 4; // 78336

    cudaFuncSetAttribute(ux_kernel,  cudaFuncAttributeMaxDynamicSharedMemorySize, smem1);
    cudaFuncSetAttribute(rec_kernel, cudaFuncAttributeMaxDynamicSharedMemorySize, smem2);

    ux_kernel<<<BSZ, 256, smem1>>>(x, U_e);
    rec_kernel<<<NBLK, NTHR, smem2>>>(W_e, V_e, W_ih, W_hh, b_ih, b_hh, out);
}

// round 5
// speedup vs baseline: 1.7706x; 1.7706x over previous
#include <cuda_runtime.h>
#include <cuda_fp16.h>

#define BSZ    2048
#define TT     128
#define NN     256
#define MM     256
#define GG4    1024
#define B_TILE 16
#define SBST   20              /* padded j-stride for state arrays (4-way instead of 16-way) */
#define NBLK   (BSZ / B_TILE)  /* 128 */
#define NTHR   512

// ---------------- device scratch (static, allowed) ----------------
__device__ __half g_Ux[(size_t)BSZ * TT * NN];       // [b][s][n] fp16, 134 MB
__device__ float4 g_Wt [128 * 1024];                 // [k4][r], r=g*256+m; k<256 -> W_ih, else W_hh
__device__ float4 g_WtE[128 * 128];                  // [k4][s] for W_e (k over [h;c])

// ---------------- fast math ----------------
__device__ __forceinline__ float ex2f(float x) {
    float r; asm("ex2.approx.f32 %0, %1;" : "=f"(r) : "f"(x)); return r;
}
__device__ __forceinline__ float rcpf(float x) {
    float r; asm("rcp.approx.f32 %0, %1;" : "=f"(r) : "f"(x)); return r;
}
#define L2E 1.4426950408889634f
__device__ __forceinline__ float tanh_fast(float x) {      // precise path (cell update)
    float t = ex2f(2.0f * L2E * x);
    return 1.0f - 2.0f * rcpf(t + 1.0f);
}
__device__ __forceinline__ float sigmoid_fast(float x) {
    return rcpf(1.0f + ex2f(-L2E * x));
}
__device__ __forceinline__ unsigned tanh2_h(unsigned x) {  // f16x2 hardware tanh (attention only)
    unsigned r; asm("tanh.approx.f16x2 %0, %1;" : "=r"(r) : "r"(x)); return r;
}

// ---------------- packed f32x2 ----------------
typedef unsigned long long u64;
__device__ __forceinline__ u64 pack2(float a, float b) {
    u64 r; asm("mov.b64 %0, {%1, %2};" : "=l"(r) : "f"(a), "f"(b)); return r;
}
__device__ __forceinline__ void unpack2(u64 v, float& a, float& b) {
    asm("mov.b64 {%0, %1}, %2;" : "=f"(a), "=f"(b) : "l"(v));
}
__device__ __forceinline__ u64 ffma2(u64 a, u64 b, u64 c) {
    u64 d; asm("fma.rn.f32x2 %0, %1, %2, %3;" : "=l"(d) : "l"(a), "l"(b), "l"(c)); return d;
}

// =====================================================================
// Kernel 0: weight transpose -> k-major float4 tiles (coalesced consumers)
// =====================================================================
__global__ void __launch_bounds__(256) wt_kernel(
    const float* __restrict__ W_ih, const float* __restrict__ W_hh,
    const float* __restrict__ W_e)
{
    int idx = blockIdx.x * 256 + threadIdx.x;
    if (idx < 128 * 1024) {
        int k4 = idx >> 10, r = idx & 1023;
        float4 v = (k4 < 64) ? ((const float4*)W_ih)[r * 64 + k4]
                             : ((const float4*)W_hh)[r * 64 + (k4 - 64)];
        g_Wt[idx] = v;
    } else {
        int j = idx - 128 * 1024;          // 0..16383
        int k4 = j >> 7, s = j & 127;
        g_WtE[j] = ((const float4*)W_e)[s * 128 + k4];
    }
}

// =====================================================================
// Kernel 1: Ux[b][s][n] = sum_t U_e[s][t] * x[b][t][n]  (fp16 output)
// grid = 2048 blocks, 256 threads (thread = n). f32x2 over s-pairs.
// =====================================================================
__global__ void __launch_bounds__(256, 1) ux_kernel(
    const float* __restrict__ x, const float* __restrict__ U_e)
{
    extern __shared__ float sm[];
    float* x_s  = sm;                // [TT][NN]  32768 floats
    u64*   U2_s = (u64*)(sm + TT * NN);  // [64 s-pairs][128 t]  8192 u64
    float* U2f  = (float*)U2_s;

    const int b   = blockIdx.x;
    const int tid = threadIdx.x;

    const float4* xg = (const float4*)(x + (size_t)b * TT * NN);
    float4* xs4 = (float4*)x_s;
    for (int i = tid; i < TT * NN / 4; i += 256) xs4[i] = xg[i];

    // U_e -> s-paired u64 layout: U2[s>>1][t] = (U[s_even][t], U[s_odd][t])
    for (int i = tid; i < TT * TT / 4; i += 256) {
        float4 v = ((const float4*)U_e)[i];
        int s  = i >> 5;            // 32 float4 per 128-float row
        int t0 = (i & 31) * 4;
        #pragma unroll
        for (int q = 0; q < 4; q++)
            U2f[(((s >> 1) * 128) + (t0 + q)) * 2 + (s & 1)] = (&v.x)[q];
    }
    __syncthreads();

    const int n = tid;
    for (int chunk = 0; chunk < 8; chunk++) {
        u64 acc[8];
        #pragma unroll
        for (int i = 0; i < 8; i++) acc[i] = 0ull;
        #pragma unroll 2
        for (int t = 0; t < TT; t++) {
            float xv = x_s[t * NN + n];
            u64 xp = pack2(xv, xv);
            #pragma unroll
            for (int i = 0; i < 8; i++)
                acc[i] = ffma2(U2_s[(chunk * 8 + i) * 128 + t], xp, acc[i]);
        }
        #pragma unroll
        for (int i = 0; i < 8; i++) {
            float a, bb; unpack2(acc[i], a, bb);
            #pragma unroll
            for (int h = 0; h < 2; h++) {
                float v = h ? bb : a;
                int s = chunk * 16 + 2 * i + h;
                float vn = __shfl_down_sync(0xffffffffu, v, 1);
                if ((n & 1) == 0) {
                    __half2 hv = __floats2half2_rn(v, vn);
                    *((__half2*)(g_Ux + ((size_t)b * TT + s) * NN + n)) = hv;
                }
            }
        }
    }
}

// =====================================================================
// Kernel 2: persistent recurrence. 128 blocks x 16 batches, 512 threads.
// =====================================================================
__global__ void __launch_bounds__(NTHR, 1) rec_kernel(
    const float* __restrict__ V_e,
    const float* __restrict__ b_ih, const float* __restrict__ b_hh,
    float* __restrict__ out)
{
    extern __shared__ float sm[];
    float*    h_s   = sm;                      // [NN][SBST]
    float*    c_s   = h_s  + NN * SBST;        // [NN][SBST]
    float*    xt_s  = c_s  + NN * SBST;        // [NN][SBST]
    float*    e_s   = xt_s + NN * SBST;        // [B_TILE][NN]
    float*    bs_s  = e_s  + B_TILE * NN;      // [GG4]
    float*    V_s   = bs_s + GG4;              // [TT]
    unsigned* whs2  = (unsigned*)(V_s + TT);   // [TT][B_TILE] half2(w,w)

    const int tid = threadIdx.x;
    const int b0  = blockIdx.x * B_TILE;

    for (int i = tid; i < NN * SBST; i += NTHR) { h_s[i] = 0.0f; c_s[i] = 0.0f; }
    for (int i = tid; i < TT;  i += NTHR) V_s[i]  = V_e[i];
    for (int i = tid; i < GG4; i += NTHR) bs_s[i] = b_ih[i] + b_hh[i];
    __syncthreads();

    // phase A: thread = (sI, 4 batches)
    const int sI  = tid & 127;
    const int j0A = (tid >> 7) * 4;
    // phase B: thread = (n-pair, 4 batches)
    const int np  = tid & 127;
    const int n0  = np * 2;
    const int jg  = tid >> 7;                  // 0..3, warp-uniform
    // phase C: warp = batch
    const int warp = tid >> 5, lane = tid & 31;
    // phase D: thread = (m, 8 batches)
    const int mD  = tid & 255;
    const int jD0 = (tid >> 8) * 8;

    const __half2* ux2[4];
    #pragma unroll
    for (int jj = 0; jj < 4; jj++)
        ux2[jj] = (const __half2*)(g_Ux + ((size_t)(b0 + jg * 4 + jj) * TT) * NN + n0);

    for (int t = 0; t < TT; t++) {
        // ---------- Phase A: whs[sI][j] = [h;c] . W_e[sI]  (coalesced g_WtE) ----------
        {
            u64 a01 = 0ull, a23 = 0ull;
            #pragma unroll 2
            for (int k4 = 0; k4 < 64; k4++) {
                float4 w = g_WtE[k4 * 128 + sI];
                #pragma unroll
                for (int q = 0; q < 4; q++) {
                    float wq = (&w.x)[q];
                    u64 wp = pack2(wq, wq);
                    ulonglong2 sv = *(const ulonglong2*)&h_s[(k4 * 4 + q) * SBST + j0A];
                    a01 = ffma2(wp, sv.x, a01); a23 = ffma2(wp, sv.y, a23);
                }
            }
            #pragma unroll 2
            for (int k4 = 64; k4 < 128; k4++) {
                float4 w = g_WtE[k4 * 128 + sI];
                #pragma unroll
                for (int q = 0; q < 4; q++) {
                    float wq = (&w.x)[q];
                    u64 wp = pack2(wq, wq);
                    ulonglong2 sv = *(const ulonglong2*)&c_s[((k4 - 64) * 4 + q) * SBST + j0A];
                    a01 = ffma2(wp, sv.x, a01); a23 = ffma2(wp, sv.y, a23);
                }
            }
            float r0, r1, r2, r3;
            unpack2(a01, r0, r1); unpack2(a23, r2, r3);
            __half2 p0 = __half2half2(__float2half_rn(r0));
            __half2 p1 = __half2half2(__float2half_rn(r1));
            __half2 p2 = __half2half2(__float2half_rn(r2));
            __half2 p3 = __half2half2(__float2half_rn(r3));
            whs2[sI * B_TILE + j0A + 0] = *(unsigned*)&p0;
            whs2[sI * B_TILE + j0A + 1] = *(unsigned*)&p1;
            whs2[sI * B_TILE + j0A + 2] = *(unsigned*)&p2;
            whs2[sI * B_TILE + j0A + 3] = *(unsigned*)&p3;
        }
        __syncthreads();

        // ---------- Phase B: e[j][n] = sum_s V[s] * tanh(Ux + whs)  (fp16 stream) ----------
        {
            float ex0[4] = {0, 0, 0, 0}, ex1[4] = {0, 0, 0, 0};
            #pragma unroll 2
            for (int s = 0; s < TT; s++) {
                uint4 wpk = *(const uint4*)&whs2[s * B_TILE + jg * 4];  // broadcast
                float vs = V_s[s];
                #pragma unroll
                for (int jj = 0; jj < 4; jj++) {
                    __half2 u   = ux2[jj][s * (NN / 2)];
                    __half2 wv  = *(__half2*)(((unsigned*)&wpk) + jj);
                    __half2 arg = __hadd2(u, wv);
                    unsigned th = tanh2_h(*(unsigned*)&arg);
                    float2 f = __half22float2(*(__half2*)&th);
                    ex0[jj] = fmaf(vs, f.x, ex0[jj]);
                    ex1[jj] = fmaf(vs, f.y, ex1[jj]);
                }
            }
            #pragma unroll
            for (int jj = 0; jj < 4; jj++) {
                float2 v = make_float2(ex0[jj], ex1[jj]);
                *(float2*)&e_s[(jg * 4 + jj) * NN + n0] = v;
            }
        }
        __syncthreads();

        // ---------- Phase C: softmax over n, xt = alpha * e ----------
        {
            const int j = warp;
            float ev[8];
            float mx = -3.4e38f;
            #pragma unroll
            for (int i = 0; i < 8; i++) {
                ev[i] = e_s[j * NN + lane + 32 * i];
                mx = fmaxf(mx, ev[i]);
            }
            #pragma unroll
            for (int o = 16; o > 0; o >>= 1) mx = fmaxf(mx, __shfl_xor_sync(0xffffffffu, mx, o));
            float ax[8], sum = 0.0f;
            #pragma unroll
            for (int i = 0; i < 8; i++) { ax[i] = ex2f((ev[i] - mx) * L2E); sum += ax[i]; }
            #pragma unroll
            for (int o = 16; o > 0; o >>= 1) sum += __shfl_xor_sync(0xffffffffu, sum, o);
            float inv = rcpf(sum);
            #pragma unroll
            for (int i = 0; i < 8; i++)
                xt_s[(lane + 32 * i) * SBST + j] = (ax[i] * inv) * ev[i];
        }
        __syncthreads();

        // ---------- Phase D: gates = [W_ih W_hh] @ [xt; h] + bias, LSTM update ----------
        {
            u64 acc[4][4];
            #pragma unroll
            for (int g = 0; g < 4; g++) {
                float bb = bs_s[g * MM + mD];
                u64 bp = pack2(bb, bb);
                #pragma unroll
                for (int p = 0; p < 4; p++) acc[g][p] = bp;
            }
            // k < 256 : xt part (coalesced g_Wt rows)
            #pragma unroll 2
            for (int k4 = 0; k4 < 64; k4++) {
                float4 w0 = g_Wt[k4 * 1024 +   0 + mD];
                float4 w1 = g_Wt[k4 * 1024 + 256 + mD];
                float4 w2 = g_Wt[k4 * 1024 + 512 + mD];
                float4 w3 = g_Wt[k4 * 1024 + 768 + mD];
                #pragma unroll
                for (int q = 0; q < 4; q++) {
                    int k = k4 * 4 + q;
                    ulonglong2 xa = *(const ulonglong2*)&xt_s[k * SBST + jD0];
                    ulonglong2 xb = *(const ulonglong2*)&xt_s[k * SBST + jD0 + 4];
                    float ws[4] = { (&w0.x)[q], (&w1.x)[q], (&w2.x)[q], (&w3.x)[q] };
                    #pragma unroll
                    for (int g = 0; g < 4; g++) {
                        u64 wp = pack2(ws[g], ws[g]);
                        acc[g][0] = ffma2(wp, xa.x, acc[g][0]);
                        acc[g][1] = ffma2(wp, xa.y, acc[g][1]);
                        acc[g][2] = ffma2(wp, xb.x, acc[g][2]);
                        acc[g][3] = ffma2(wp, xb.y, acc[g][3]);
                    }
                }
            }
            // k >= 256 : h part
            #pragma unroll 2
            for (int k4 = 64; k4 < 128; k4++) {
                float4 w0 = g_Wt[k4 * 1024 +   0 + mD];
                float4 w1 = g_Wt[k4 * 1024 + 256 + mD];
                float4 w2 = g_Wt[k4 * 1024 + 512 + mD];
                float4 w3 = g_Wt[k4 * 1024 + 768 + mD];
                #pragma unroll
                for (int q = 0; q < 4; q++) {
                    int k = (k4 - 64) * 4 + q;
                    ulonglong2 ha = *(const ulonglong2*)&h_s[k * SBST + jD0];
                    ulonglong2 hb = *(const ulonglong2*)&h_s[k * SBST + jD0 + 4];
                    float ws[4] = { (&w0.x)[q], (&w1.x)[q], (&w2.x)[q], (&w3.x)[q] };
                    #pragma unroll
                    for (int g = 0; g < 4; g++) {
                        u64 wp = pack2(ws[g], ws[g]);
                        acc[g][0] = ffma2(wp, ha.x, acc[g][0]);
                        acc[g][1] = ffma2(wp, ha.y, acc[g][1]);
                        acc[g][2] = ffma2(wp, hb.x, acc[g][2]);
                        acc[g][3] = ffma2(wp, hb.y, acc[g][3]);
                    }
                }
            }
            float cold[8];
            #pragma unroll
            for (int jj = 0; jj < 8; jj++) cold[jj] = c_s[mD * SBST + jD0 + jj];
            __syncthreads();   // all reads of h_s/xt_s/c_s complete before writes

            #pragma unroll
            for (int p = 0; p < 4; p++) {
                float iv[2], fv[2], gv[2], ov[2];
                unpack2(acc[0][p], iv[0], iv[1]);
                unpack2(acc[1][p], fv[0], fv[1]);
                unpack2(acc[2][p], gv[0], gv[1]);
                unpack2(acc[3][p], ov[0], ov[1]);
                #pragma unroll
                for (int h2 = 0; h2 < 2; h2++) {
                    int jj = 2 * p + h2;
                    float cn = sigmoid_fast(fv[h2]) * cold[jj]
                             + sigmoid_fast(iv[h2]) * tanh_fast(gv[h2]);
                    float hn = sigmoid_fast(ov[h2]) * tanh_fast(cn);
                    c_s[mD * SBST + jD0 + jj] = cn;
                    h_s[mD * SBST + jD0 + jj] = hn;
                    out[(size_t)(b0 + jD0 + jj) * (MM * TT) + (size_t)mD * TT + t] = hn;
                }
            }
        }
        __syncthreads();   // state visible before next step
    }
}

extern "C" void kernel_launch(void* const* d_in, const int* in_sizes, int n_in,
                              void* d_out, int out_size)
{
    const float* x    = (const float*)d_in[0];
    const float* W_e  = (const float*)d_in[1];
    const float* U_e  = (const float*)d_in[2];
    const float* V_e  = (const float*)d_in[3];
    const float* W_ih = (const float*)d_in[4];
    const float* W_hh = (const float*)d_in[5];
    const float* b_ih = (const float*)d_in[6];
    const float* b_hh = (const float*)d_in[7];
    float* out = (float*)d_out;

    const int smem1 = (TT * NN) * 4 + 64 * 128 * 8;                       // 196608
    const int smem2 = (3 * NN * SBST + B_TILE * NN + GG4 + TT) * 4
                    + TT * B_TILE * 4;                                     // ~90 KB

    cudaFuncSetAttribute(ux_kernel,  cudaFuncAttributeMaxDynamicSharedMemorySize, smem1);
    cudaFuncSetAttribute(rec_kernel, cudaFuncAttributeMaxDynamicSharedMemorySize, smem2);

    wt_kernel<<<(128 * 1024 + 128 * 128) / 256, 256>>>(W_ih, W_hh, W_e);
    ux_kernel<<<BSZ, 256, smem1>>>(x, U_e);
    rec_kernel<<<NBLK, NTHR, smem2>>>(V_e, b_ih, b_hh, out);
}